// round 11
// baseline (speedup 1.0000x reference)
#include <cuda_runtime.h>
#include <math.h>
#include <stdint.h>

// Problem constants
#define N_ROWS 2048
#define D_DIM  192
#define C_CLS  100000
#define S_SCALE 30.0f
#define MARGIN  0.2f

#define NT256 391         // class tiles of 256 (391*256 = 100096)
#define CPAD  100096
#define STRIPES 37        // grid (37,16) = 592 CTAs = 4 waves @ 1 CTA/SM (512 thr)
#define NPART (STRIPES * 8)   // 296 partials per row
#define B_CLS 256

// ---------------- scratch globals ----------------
__device__ __align__(16) float g_xn[N_ROWS * D_DIM];
__device__ __align__(16) unsigned short g_wbf[(size_t)CPAD * D_DIM];  // bf16, k-pair permuted
__device__ float g_tgt[N_ROWS];
__device__ float g_psum[(size_t)N_ROWS * NPART];
__device__ float g_L[N_ROWS];
__device__ int   g_lab32;

// ---------------- helpers (sm_80-level PTX only) ----------------
// pack(lo, hi): bf16x2 register {hi:lo}
__device__ __forceinline__ uint32_t bfpack(float lo, float hi) {
    uint32_t r;
    asm("cvt.rn.bf16x2.f32 %0, %1, %2;" : "=r"(r) : "f"(hi), "f"(lo));
    return r;
}

__device__ __forceinline__ void mma16(float* c, const uint32_t* a, uint32_t b0, uint32_t b1) {
    asm volatile(
        "mma.sync.aligned.m16n8k16.row.col.f32.bf16.bf16.f32 "
        "{%0,%1,%2,%3}, {%4,%5,%6,%7}, {%8,%9}, {%0,%1,%2,%3};"
        : "+f"(c[0]), "+f"(c[1]), "+f"(c[2]), "+f"(c[3])
        : "r"(a[0]), "r"(a[1]), "r"(a[2]), "r"(a[3]), "r"(b0), "r"(b1));
}

// exp(S*d) = 2^(S*log2(e)*d) via MUFU ex2
__device__ __forceinline__ float exp_s(float d) {
    float r;
    asm("ex2.approx.f32 %0, %1;" : "=f"(r) : "f"(43.2808512266689f * d));
    return r;
}

// ---------------------------------------------------------------------------
// Kernel 0: label dtype detect (touches only first 8KB; safe either way)
// ---------------------------------------------------------------------------
__global__ void detect_label_kernel(const int* __restrict__ lab) {
    __shared__ int any;
    if (threadIdx.x == 0) any = 0;
    __syncthreads();
    int v = 0;
    for (int i = threadIdx.x; i < 1024; i += blockDim.x) v |= lab[2 * i + 1];
    if (v) atomicOr(&any, 1);
    __syncthreads();
    if (threadIdx.x == 0) g_lab32 = (any != 0) ? 1 : 0;
}

// ---------------------------------------------------------------------------
// Kernel 0b: W (f32) -> g_wbf (bf16), permuted per k16 block so a B fragment
// (k pairs {2qt,2qt+1} and {2qt+8,2qt+9}) is one aligned 8-byte word pair.
// Word order per k16: (0,1)(8,9)(2,3)(10,11)(4,5)(12,13)(6,7)(14,15).
// ---------------------------------------------------------------------------
__global__ void convertW_kernel(const float* __restrict__ W) {
    int idx = blockIdx.x * blockDim.x + threadIdx.x;   // (cls, ks) pair
    if (idx >= CPAD * 12) return;
    int cls = idx / 12, ks = idx % 12;
    int cr = cls < C_CLS ? cls : C_CLS - 1;
    const float* wr = W + (size_t)cr * D_DIM + ks * 16;
    float v[16];
#pragma unroll
    for (int j = 0; j < 4; j++) {
        float4 t = ((const float4*)wr)[j];
        v[4 * j] = t.x; v[4 * j + 1] = t.y; v[4 * j + 2] = t.z; v[4 * j + 3] = t.w;
    }
    const int ps[8] = {0, 8, 2, 10, 4, 12, 6, 14};
    uint32_t o[8];
#pragma unroll
    for (int j = 0; j < 8; j++) o[j] = bfpack(v[ps[j]], v[ps[j] + 1]);
    uint4* dst = (uint4*)(g_wbf + (size_t)cls * D_DIM + ks * 16);
    dst[0] = make_uint4(o[0], o[1], o[2], o[3]);
    dst[1] = make_uint4(o[4], o[5], o[6], o[7]);
}

// ---------------------------------------------------------------------------
// Kernel 1: row normalize + exact target logit (fp32)
// ---------------------------------------------------------------------------
__global__ void norm_tgt_kernel(const float* __restrict__ x,
                                const float* __restrict__ W,
                                const void* __restrict__ label) {
    int warp = (blockIdx.x * blockDim.x + threadIdx.x) >> 5;
    int lane = threadIdx.x & 31;
    if (warp >= N_ROWS) return;

    const float* xr = x + (size_t)warp * D_DIM;
    float xv[6], ss = 0.f;
#pragma unroll
    for (int j = 0; j < 6; j++) { xv[j] = xr[lane + 32 * j]; ss += xv[j] * xv[j]; }
#pragma unroll
    for (int o = 16; o; o >>= 1) ss += __shfl_xor_sync(0xffffffffu, ss, o);
    float inv = rsqrtf(ss);

    long long li = g_lab32 ? (long long)((const int*)label)[warp]
                           : ((const long long*)label)[warp];
    if (li < 0) li = 0;
    if (li >= C_CLS) li = C_CLS - 1;

    const float* wr = W + (size_t)li * D_DIM;
    float dot = 0.f;
#pragma unroll
    for (int j = 0; j < 6; j++) {
        g_xn[(size_t)warp * D_DIM + lane + 32 * j] = xv[j] * inv;
        dot += xv[j] * wr[lane + 32 * j];
    }
#pragma unroll
    for (int o = 16; o; o >>= 1) dot += __shfl_xor_sync(0xffffffffu, dot, o);
    if (lane == 0) g_tgt[warp] = dot * inv;
}

// ---------------------------------------------------------------------------
// Kernel 2: bf16 mma.sync m16n8k16 GEMM, 128 rows x 256 classes per tile.
// B streamed gmem->registers via LDG.64 with a 3-slot, distance-2 prefetch
// ring — NO smem staging for B, NO barriers in the main loop (A is read-only
// smem after the prologue). 512 threads, 16 warps free-running.
//   warp grid 2(m) x 8(n); warp tile 64x32; 4(mt) x 4(nt) fragments.
// ---------------------------------------------------------------------------
__global__ void __launch_bounds__(512, 1) gemm_lse_mma() {
    __shared__ uint4 As4[96 * 32];        // [96 frags][32 lanes] = 48 KB

    const int tid  = threadIdx.x;
    const int wid  = tid >> 5;
    const int lane = tid & 31;
    const int wm = wid >> 3, wn = wid & 7;
    const int qid = lane >> 2, qt = lane & 3;
    const int rowBase = blockIdx.y * 128;
    const int ct0 = blockIdx.x;

    // ---- stage A once as bf16 m16n8k16 fragments ----
    // frag f = fm*12 + ks; fm = 16-row group (0..7), ks = k16 step (0..11)
    for (int f = wid; f < 96; f += 16) {
        int fm = f / 12, ks = f % 12;
        const float* b0 = g_xn + (size_t)(rowBase + fm * 16 + qid) * D_DIM + ks * 16 + 2 * qt;
        const float* b8 = b0 + 8 * D_DIM;
        As4[f * 32 + lane] = make_uint4(
            bfpack(b0[0], b0[1]), bfpack(b8[0], b8[1]),
            bfpack(b0[8], b0[9]), bfpack(b8[8], b8[9]));
    }
    __syncthreads();      // the only block barrier

    const uint2* __restrict__ gw2 = (const uint2*)g_wbf;   // 48 uint2 per class row
    const int ntiles = (NT256 - 1 - ct0) / STRIPES + 1;

    // B fragment fetch for (ct, ks, nt): lane reads 8B at cls*48 + ks*4 + qt
    const int clsLane = wn * 32 + qid;   // class offset of this lane within tile
    auto fetchB = [&](uint2* dst, int ct, int ks) {
        size_t base = ((size_t)(ct * B_CLS + clsLane)) * 48 + ks * 4 + qt;
#pragma unroll
        for (int nt = 0; nt < 4; nt++)
            dst[nt] = gw2[base + (size_t)nt * 8 * 48];
    };

    uint2 bring[3][4];    // prefetch ring, distance 2
    fetchB(bring[0], ct0, 0);
    fetchB(bring[1], ct0, 1);

    float rsum[4][2] = {};
    float acc[4][4][4];

    const uint4* af0 = As4 + (wm * 4) * 12 * 32 + lane;

    for (int t = 0; t < ntiles; t++) {
        const int ct  = ct0 + t * STRIPES;
        const int ctn = (t + 1 < ntiles) ? ct + STRIPES : ct;

#pragma unroll
        for (int ks = 0; ks < 12; ks++) {
            // prefetch (ks+2) into the slot freed last iteration
            {
                const int kq  = (ks + 2 < 12) ? ks + 2 : ks - 10;
                const int ctp = (ks + 2 < 12) ? ct : ctn;
                fetchB(bring[(ks + 2) % 3], ctp, kq);
            }

            if (ks == 0) {
#pragma unroll
                for (int mt = 0; mt < 4; mt++)
#pragma unroll
                    for (int nt = 0; nt < 4; nt++)
#pragma unroll
                        for (int e = 0; e < 4; e++) acc[mt][nt][e] = 0.f;
            }

            uint4 a[4];
#pragma unroll
            for (int mt = 0; mt < 4; mt++)
                a[mt] = af0[(mt * 12 + ks) * 32];

            const uint2* b = bring[ks % 3];
#pragma unroll
            for (int nt = 0; nt < 4; nt++)
#pragma unroll
                for (int mt = 0; mt < 4; mt++)
                    mma16(acc[mt][nt], (const uint32_t*)&a[mt], b[nt].x, b[nt].y);

            if (ks == 11) {
                if (ct != NT256 - 1) {
#pragma unroll
                    for (int mt = 0; mt < 4; mt++)
#pragma unroll
                        for (int nt = 0; nt < 4; nt++) {
                            rsum[mt][0] += exp_s(acc[mt][nt][0]) + exp_s(acc[mt][nt][1]);
                            rsum[mt][1] += exp_s(acc[mt][nt][2]) + exp_s(acc[mt][nt][3]);
                        }
                } else {
#pragma unroll
                    for (int mt = 0; mt < 4; mt++)
#pragma unroll
                        for (int nt = 0; nt < 4; nt++) {
                            int cls0 = ct * B_CLS + wn * 32 + nt * 8 + 2 * qt;
                            if (cls0 < C_CLS)     { rsum[mt][0] += exp_s(acc[mt][nt][0]);
                                                    rsum[mt][1] += exp_s(acc[mt][nt][2]); }
                            if (cls0 + 1 < C_CLS) { rsum[mt][0] += exp_s(acc[mt][nt][1]);
                                                    rsum[mt][1] += exp_s(acc[mt][nt][3]); }
                        }
                }
            }
        }
    }

    // ---- one partial per (stripe, wn) per row ----
    const int cidx = blockIdx.x * 8 + wn;
#pragma unroll
    for (int mt = 0; mt < 4; mt++) {
        float sLo = rsum[mt][0], sHi = rsum[mt][1];
        sLo += __shfl_xor_sync(0xffffffffu, sLo, 1);
        sLo += __shfl_xor_sync(0xffffffffu, sLo, 2);
        sHi += __shfl_xor_sync(0xffffffffu, sHi, 1);
        sHi += __shfl_xor_sync(0xffffffffu, sHi, 2);
        if (qt == 0) {
            int row = rowBase + wm * 64 + mt * 16 + qid;
            g_psum[(size_t)row * NPART + cidx]       = sLo;
            g_psum[(size_t)(row + 8) * NPART + cidx] = sHi;
        }
    }
}

// ---------------------------------------------------------------------------
// Kernel 3: warp per row: sum 296 partials + margin correction
// ---------------------------------------------------------------------------
__global__ void combine_kernel() {
    int row  = blockIdx.x * 8 + (threadIdx.x >> 5);
    int lane = threadIdx.x & 31;
    const float* p = g_psum + (size_t)row * NPART;
    float s = 0.f;
    for (int c = lane; c < NPART; c += 32) s += p[c];
#pragma unroll
    for (int o = 16; o; o >>= 1) s += __shfl_xor_sync(0xffffffffu, s, o);
    if (lane == 0) {
        float tgt   = g_tgt[row];
        float numer = S_SCALE * (tgt - MARGIN);
        float scorr = s - expf(S_SCALE * tgt) + expf(numer);
        g_L[row] = numer - logf(scorr);
    }
}

// ---------------------------------------------------------------------------
// Kernel 4: mean
// ---------------------------------------------------------------------------
__global__ void final_kernel(float* __restrict__ out) {
    __shared__ float sm[1024];
    int t = threadIdx.x;
    sm[t] = g_L[t] + g_L[t + 1024];
    __syncthreads();
    for (int st = 512; st > 0; st >>= 1) {
        if (t < st) sm[t] += sm[t + st];
        __syncthreads();
    }
    if (t == 0) out[0] = -sm[0] / (float)N_ROWS;
}

// ---------------------------------------------------------------------------
extern "C" void kernel_launch(void* const* d_in, const int* in_sizes, int n_in,
                              void* d_out, int out_size) {
    (void)in_sizes; (void)n_in; (void)out_size;
    const float* x     = (const float*)d_in[0];
    const float* W     = (const float*)d_in[1];
    const void*  label = d_in[2];
    float* out = (float*)d_out;

    detect_label_kernel<<<1, 256>>>((const int*)label);
    convertW_kernel<<<(CPAD * 12 + 255) / 256, 256>>>(W);
    norm_tgt_kernel<<<N_ROWS / 8, 256>>>(x, W, label);

    dim3 grid(STRIPES, N_ROWS / 128);
    gemm_lse_mma<<<grid, 512>>>();

    combine_kernel<<<N_ROWS / 8, 256>>>();
    final_kernel<<<1, 1024>>>(out);
}